// round 8
// baseline (speedup 1.0000x reference)
#include <cuda_runtime.h>
#include <cstdint>
#include <mma.h>
#include <math.h>

using namespace nvcuda;

#define Bb   8
#define Ss   2048
#define Hh   8
#define IDd  256
#define ODd  256
#define KTOT 512
#define MTOT (Bb*Ss*Hh)       // 131072 tokens
#define BSN  (Bb*Ss)          // 16384

#define BM   128
#define BN   64
#define BK   32
#define BKP  36
#define CLD  68
#define NT   (KTOT/BK)        // 16
#define NCHUNK 16
#define CH   (Ss/NCHUNK)      // 128

// ---------------- scratch ----------------------------------------------------
__device__ float g_csum [(size_t)MTOT * IDd];    // 128 MB (raw csum, fp32)
__device__ float g_x2   [(size_t)MTOT * KTOT];   // 256 MB (tf32-rounded [in | LN(csum)])
__device__ float g_f    [(size_t)MTOT * ODd];
__device__ float g_igh  [(size_t)MTOT * ODd];
__device__ float g_cell [(size_t)MTOT * ODd];    // fp32 cell (epilogue multiply)
__device__ float g_cellt[(size_t)MTOT * ODd];    // tf32-rounded cell (gemm2 A)
__device__ float g_whc  [3 * ODd * KTOT];        // tf32-rounded W_hid
__device__ float g_woc  [ODd * KTOT];            // tf32-rounded W_og
__device__ float g_psum [64 * NCHUNK * 256];
__device__ float g_mean [BSN];
__device__ float g_rstd [BSN];

__device__ __forceinline__ float sigmoidf_(float x) { return 1.f / (1.f + expf(-x)); }

__device__ __forceinline__ void cpa16(uint32_t dst, const void* src) {
    asm volatile("cp.async.cg.shared.global [%0], [%1], 16;\n" :: "r"(dst), "l"(src));
}
__device__ __forceinline__ void cpa_commit() { asm volatile("cp.async.commit_group;\n"); }
__device__ __forceinline__ void cpa_wait0()  { asm volatile("cp.async.wait_group 0;\n"); }

// ---------------- K1a: per-chunk sums ---------------------------------------
__global__ void k_cumsum_p1(const float* __restrict__ in) {
    int bh = blockIdx.x, chunk = blockIdx.y, d = threadIdx.x;
    int b = bh >> 3, h = bh & 7;
    const size_t stride = (size_t)Hh * IDd;
    size_t idx = ((size_t)b * Ss * Hh + h) * IDd + d + (size_t)chunk * CH * stride;
    float s = 0.f;
    for (int j = 0; j < CH; j += 8) {
        float v[8];
#pragma unroll
        for (int t = 0; t < 8; t++) v[t] = in[idx + (size_t)(j + t) * stride];
#pragma unroll
        for (int t = 0; t < 8; t++) s += v[t];
    }
    g_psum[(bh * NCHUNK + chunk) * 256 + d] = s;
}

// ---------------- K1b: emit csum with chunk offset ---------------------------
__global__ void k_cumsum_p2(const float* __restrict__ in) {
    int bh = blockIdx.x, chunk = blockIdx.y, d = threadIdx.x;
    int b = bh >> 3, h = bh & 7;
    const size_t stride = (size_t)Hh * IDd;
    size_t idx = ((size_t)b * Ss * Hh + h) * IDd + d + (size_t)chunk * CH * stride;
    float acc = 0.f;
    for (int c = 0; c < chunk; c++) acc += g_psum[(bh * NCHUNK + c) * 256 + d];
    for (int j = 0; j < CH; j += 8) {
        float v[8];
#pragma unroll
        for (int t = 0; t < 8; t++) v[t] = in[idx + (size_t)(j + t) * stride];
#pragma unroll
        for (int t = 0; t < 8; t++) {
            acc += v[t];
            g_csum[idx + (size_t)(j + t) * stride] = acc;
        }
    }
}

// ---------------- K2: per-(b,s) stats over H*ID=2048 -------------------------
__global__ void k_stats() {
    size_t base = (size_t)blockIdx.x * 2048;
    float s1 = 0.f, s2 = 0.f;
    for (int i = threadIdx.x; i < 2048; i += 256) {
        float v = g_csum[base + i];
        s1 += v; s2 += v * v;
    }
#pragma unroll
    for (int o = 16; o; o >>= 1) {
        s1 += __shfl_down_sync(0xffffffffu, s1, o);
        s2 += __shfl_down_sync(0xffffffffu, s2, o);
    }
    __shared__ float a1[8], a2[8];
    int w = threadIdx.x >> 5, l = threadIdx.x & 31;
    if (l == 0) { a1[w] = s1; a2[w] = s2; }
    __syncthreads();
    if (threadIdx.x == 0) {
        float t1 = 0.f, t2 = 0.f;
#pragma unroll
        for (int i = 0; i < 8; i++) { t1 += a1[i]; t2 += a2[i]; }
        float mean = t1 * (1.f / 2048.f);
        float var  = t2 * (1.f / 2048.f) - mean * mean;
        g_mean[blockIdx.x] = mean;
        g_rstd[blockIdx.x] = rsqrtf(var + 1e-6f);
    }
}

// ---------------- K3: build x2 = tf32([in | LN(csum)]) ----------------------
__global__ void k_norm(const float* __restrict__ in,
                       const float* __restrict__ lnw,
                       const float* __restrict__ lnb) {
    int gi = blockIdx.x * 256 + threadIdx.x;      // one float4 each; MTOT*128 total
    int m    = gi >> 7;                           // token
    int part = gi & 127;                          // 0..127 float4 within 512 cols
    float4 o;
    if (part < 64) {
        float4 x = ((const float4*)(in + (size_t)m * IDd))[part];
        o.x = wmma::__float_to_tf32(x.x); o.y = wmma::__float_to_tf32(x.y);
        o.z = wmma::__float_to_tf32(x.z); o.w = wmma::__float_to_tf32(x.w);
    } else {
        int d4 = part - 64;
        int h  = m & 7;
        float mu = g_mean[m >> 3], rs = g_rstd[m >> 3];
        float4 c = ((const float4*)(g_csum + (size_t)m * IDd))[d4];
        float4 w = ((const float4*)(lnw + h * IDd))[d4];
        float4 b = ((const float4*)(lnb + h * IDd))[d4];
        o.x = wmma::__float_to_tf32((c.x - mu) * rs * w.x + b.x);
        o.y = wmma::__float_to_tf32((c.y - mu) * rs * w.y + b.y);
        o.z = wmma::__float_to_tf32((c.z - mu) * rs * w.z + b.z);
        o.w = wmma::__float_to_tf32((c.w - mu) * rs * w.w + b.w);
    }
    ((float4*)(g_x2 + (size_t)m * KTOT))[part] = o;
}

// ---------------- K3b: round weights to tf32 ---------------------------------
__global__ void k_wconv(const float* __restrict__ Wh, const float* __restrict__ Wo) {
    int i = blockIdx.x * 256 + threadIdx.x;       // over (768+256)*512/4 float4s
    const int NH = 3 * ODd * KTOT / 4;
    float4 x; float* dst;
    if (i < NH) { x = ((const float4*)Wh)[i]; dst = g_whc + i * 4; }
    else        { x = ((const float4*)Wo)[i - NH]; dst = g_woc + (i - NH) * 4; }
    dst[0] = wmma::__float_to_tf32(x.x); dst[1] = wmma::__float_to_tf32(x.y);
    dst[2] = wmma::__float_to_tf32(x.z); dst[3] = wmma::__float_to_tf32(x.w);
}

// ---------------- K4: GEMM1 (3 gates), cp.async double-buffered --------------
__global__ __launch_bounds__(512, 1)
void k_gemm1(const float* __restrict__ bhid) {
    extern __shared__ float smem[];
    float* As = smem;                          // 2 x [BM][BKP]
    float* Bs = smem + 2 * BM * BKP;           // 2 x [3*BN][BKP]
    float* Cs = smem;                          // epilogue alias [BM][CLD]

    const int tid  = threadIdx.x;
    const int n0   = blockIdx.x * BN;          // n-tile fastest -> A L2 reuse
    const int m0   = blockIdx.y * BM;
    const int warp = tid >> 5;
    const int wr   = warp >> 2;                // 0..3
    const int wc   = warp & 3;                 // 0..3

    uint32_t As_u = (uint32_t)__cvta_generic_to_shared(As);
    uint32_t Bs_u = (uint32_t)__cvta_generic_to_shared(Bs);
    const int ABUF = BM * BKP * 4;             // bytes per A buffer
    const int BBUF = 3 * BN * BKP * 4;

    wmma::fragment<wmma::accumulator, 16, 16, 8, float> acc[2][3];
#pragma unroll
    for (int t = 0; t < 2; t++)
#pragma unroll
        for (int g = 0; g < 3; g++) wmma::fill_fragment(acc[t][g], 0.f);

    auto issue = [&](int kt, int buf) {
        // A: 128x32 floats = 1024 f4 chunks, 2 per thread
#pragma unroll
        for (int i = 0; i < 2; i++) {
            int ca = tid * 2 + i;
            int r = ca >> 3, cg = ca & 7;
            const float* src = g_x2 + (size_t)(m0 + r) * KTOT + kt * BK + cg * 4;
            cpa16(As_u + buf * ABUF + (r * BKP + cg * 4) * 4, src);
        }
        // B: 3*64x32 = 1536 f4 chunks, 3 per thread
#pragma unroll
        for (int i = 0; i < 3; i++) {
            int cb = tid * 3 + i;
            int g = cb >> 9, rr = (cb >> 3) & 63, cg = cb & 7;
            const float* src = g_whc + (size_t)(g * ODd + n0 + rr) * KTOT + kt * BK + cg * 4;
            cpa16(Bs_u + buf * BBUF + ((g * BN + rr) * BKP + cg * 4) * 4, src);
        }
    };

    issue(0, 0); cpa_commit();
    for (int kt = 0; kt < NT; kt++) {
        cpa_wait0();
        __syncthreads();
        if (kt + 1 < NT) { issue(kt + 1, (kt + 1) & 1); cpa_commit(); }
        const float* Ab = As + (kt & 1) * BM * BKP;
        const float* Bbuf = Bs + (kt & 1) * 3 * BN * BKP;
#pragma unroll
        for (int ks = 0; ks < BK / 8; ks++) {
            wmma::fragment<wmma::matrix_a, 16, 16, 8, wmma::precision::tf32, wmma::row_major> af[2];
            wmma::load_matrix_sync(af[0], Ab + (wr * 32     ) * BKP + ks * 8, BKP);
            wmma::load_matrix_sync(af[1], Ab + (wr * 32 + 16) * BKP + ks * 8, BKP);
#pragma unroll
            for (int g = 0; g < 3; g++) {
                wmma::fragment<wmma::matrix_b, 16, 16, 8, wmma::precision::tf32, wmma::col_major> bf;
                wmma::load_matrix_sync(bf, Bbuf + (g * BN + wc * 16) * BKP + ks * 8, BKP);
                wmma::mma_sync(acc[0][g], af[0], bf, acc[0][g]);
                wmma::mma_sync(acc[1][g], af[1], bf, acc[1][g]);
            }
        }
        __syncthreads();
    }

    // epilogue: fgate -> g_f ; igate (regs) ; hidden -> combine -> g_igh
    float igv[16];

#pragma unroll
    for (int t = 0; t < 2; t++)
        wmma::store_matrix_sync(Cs + (wr * 32 + t * 16) * CLD + wc * 16, acc[t][1], CLD, wmma::mem_row_major);
    __syncthreads();
#pragma unroll
    for (int j = 0; j < 16; j++) {
        int e = tid + j * 512, r = e >> 6, c = e & 63;
        float v = Cs[r * CLD + c] + bhid[ODd + n0 + c];
        g_f[(size_t)(m0 + r) * ODd + n0 + c] = sigmoidf_(v);
    }
    __syncthreads();

#pragma unroll
    for (int t = 0; t < 2; t++)
        wmma::store_matrix_sync(Cs + (wr * 32 + t * 16) * CLD + wc * 16, acc[t][0], CLD, wmma::mem_row_major);
    __syncthreads();
#pragma unroll
    for (int j = 0; j < 16; j++) {
        int e = tid + j * 512, r = e >> 6, c = e & 63;
        igv[j] = sigmoidf_(Cs[r * CLD + c] + bhid[n0 + c]);
    }
    __syncthreads();

#pragma unroll
    for (int t = 0; t < 2; t++)
        wmma::store_matrix_sync(Cs + (wr * 32 + t * 16) * CLD + wc * 16, acc[t][2], CLD, wmma::mem_row_major);
    __syncthreads();
#pragma unroll
    for (int j = 0; j < 16; j++) {
        int e = tid + j * 512, r = e >> 6, c = e & 63;
        float hv = Cs[r * CLD + c] + bhid[2 * ODd + n0 + c];
        hv = hv > 0.f ? hv : 0.f;
        g_igh[(size_t)(m0 + r) * ODd + n0 + c] = igv[j] * hv;
    }
}

// ---------------- K5: sequential scan ----------------------------------------
__global__ void k_scan(const float* __restrict__ init_cx) {
    int lane = blockIdx.x * 128 + threadIdx.x;     // 0..16383
    int od = lane & 255;
    int bh = lane >> 8;
    int h  = bh & 7;
    float c = init_cx[h * ODd + od];
    size_t idx = ((size_t)(bh >> 3) * Ss * Hh + h) * ODd + od;
    const size_t stride = (size_t)Hh * ODd;
    for (int s0 = 0; s0 < Ss; s0 += 16) {
        float fv[16], iv[16];
#pragma unroll
        for (int j = 0; j < 16; j++) {
            fv[j] = g_f  [idx + (size_t)j * stride];
            iv[j] = g_igh[idx + (size_t)j * stride];
        }
#pragma unroll
        for (int j = 0; j < 16; j++) {
            c = fv[j] * c + iv[j];
            g_cell [idx + (size_t)j * stride] = c;
            g_cellt[idx + (size_t)j * stride] = wmma::__float_to_tf32(c);
        }
        idx += 16 * stride;
    }
}

// ---------------- K6: GEMM2 + output gate ------------------------------------
__global__ __launch_bounds__(512, 1)
void k_gemm2(const float* __restrict__ bo, float* __restrict__ out) {
    extern __shared__ float smem[];
    float* As = smem;                          // 2 x [BM][BKP]
    float* Bs = smem + 2 * BM * BKP;           // 2 x [BN][BKP]
    float* Cs = smem;                          // alias [BM][CLD]

    const int tid  = threadIdx.x;
    const int n0   = blockIdx.x * BN;
    const int m0   = blockIdx.y * BM;
    const int warp = tid >> 5;
    const int wr   = warp >> 2, wc = warp & 3;

    uint32_t As_u = (uint32_t)__cvta_generic_to_shared(As);
    uint32_t Bs_u = (uint32_t)__cvta_generic_to_shared(Bs);
    const int ABUF = BM * BKP * 4;
    const int BBUF = BN * BKP * 4;

    wmma::fragment<wmma::accumulator, 16, 16, 8, float> acc[2];
    wmma::fill_fragment(acc[0], 0.f);
    wmma::fill_fragment(acc[1], 0.f);

    auto issue = [&](int kt, int buf) {
#pragma unroll
        for (int i = 0; i < 2; i++) {
            int ca = tid * 2 + i;
            int r = ca >> 3, cg = ca & 7;
            int gcol = kt * BK + cg * 4;
            const float* src = (gcol < IDd)
                ? (g_x2   + (size_t)(m0 + r) * KTOT + gcol)
                : (g_cellt + (size_t)(m0 + r) * ODd + (gcol - IDd));
            cpa16(As_u + buf * ABUF + (r * BKP + cg * 4) * 4, src);
        }
        {
            int cb = tid;                      // 512 chunks exactly
            int rr = cb >> 3, cg = cb & 7;
            const float* src = g_woc + (size_t)(n0 + rr) * KTOT + kt * BK + cg * 4;
            cpa16(Bs_u + buf * BBUF + (rr * BKP + cg * 4) * 4, src);
        }
    };

    issue(0, 0); cpa_commit();
    for (int kt = 0; kt < NT; kt++) {
        cpa_wait0();
        __syncthreads();
        if (kt + 1 < NT) { issue(kt + 1, (kt + 1) & 1); cpa_commit(); }
        const float* Ab = As + (kt & 1) * BM * BKP;
        const float* Bbuf = Bs + (kt & 1) * BN * BKP;
#pragma unroll
        for (int ks = 0; ks < BK / 8; ks++) {
            wmma::fragment<wmma::matrix_a, 16, 16, 8, wmma::precision::tf32, wmma::row_major> af[2];
            wmma::load_matrix_sync(af[0], Ab + (wr * 32     ) * BKP + ks * 8, BKP);
            wmma::load_matrix_sync(af[1], Ab + (wr * 32 + 16) * BKP + ks * 8, BKP);
            wmma::fragment<wmma::matrix_b, 16, 16, 8, wmma::precision::tf32, wmma::col_major> bf;
            wmma::load_matrix_sync(bf, Bbuf + (wc * 16) * BKP + ks * 8, BKP);
            wmma::mma_sync(acc[0], af[0], bf, acc[0]);
            wmma::mma_sync(acc[1], af[1], bf, acc[1]);
        }
        __syncthreads();
    }

#pragma unroll
    for (int t = 0; t < 2; t++)
        wmma::store_matrix_sync(Cs + (wr * 32 + t * 16) * CLD + wc * 16, acc[t], CLD, wmma::mem_row_major);
    __syncthreads();
#pragma unroll
    for (int j = 0; j < 16; j++) {
        int e = tid + j * 512, r = e >> 6, c = e & 63;
        float v = Cs[r * CLD + c] + bo[n0 + c];
        size_t o = (size_t)(m0 + r) * ODd + n0 + c;
        out[o] = sigmoidf_(v) * g_cell[o];
    }
}

// ---------------- launcher ---------------------------------------------------
extern "C" void kernel_launch(void* const* d_in, const int* in_sizes, int n_in,
                              void* d_out, int out_size) {
    const float* in      = (const float*)d_in[0];
    const float* W_hid   = (const float*)d_in[1];
    const float* b_hid   = (const float*)d_in[2];
    const float* W_og    = (const float*)d_in[3];
    const float* b_og    = (const float*)d_in[4];
    const float* ln_w    = (const float*)d_in[5];
    const float* ln_b    = (const float*)d_in[6];
    const float* init_cx = (const float*)d_in[7];
    float* out = (float*)d_out;

    size_t smem1 = (size_t)(2 * BM * BKP + 2 * 3 * BN * BKP) * sizeof(float);  // 92160
    size_t smem2 = (size_t)(2 * BM * BKP + 2 * BN * BKP) * sizeof(float);      // 55296
    cudaFuncSetAttribute(k_gemm1, cudaFuncAttributeMaxDynamicSharedMemorySize, (int)smem1);
    cudaFuncSetAttribute(k_gemm2, cudaFuncAttributeMaxDynamicSharedMemorySize, (int)smem2);

    k_wconv<<<(3 * ODd * KTOT + ODd * KTOT) / 4 / 256, 256>>>(W_hid, W_og);

    dim3 gcs(Bb * Hh, NCHUNK);
    k_cumsum_p1<<<gcs, 256>>>(in);
    k_cumsum_p2<<<gcs, 256>>>(in);
    k_stats<<<BSN, 256>>>();
    k_norm<<<(MTOT * 128) / 256, 256>>>(in, ln_w, ln_b);

    dim3 g1(ODd / BN, MTOT / BM);          // n fastest -> A tile L2 reuse
    k_gemm1<<<g1, 512, smem1>>>(b_hid);

    k_scan<<<(Bb * Hh * ODd) / 128, 128>>>(init_cx);

    dim3 g2(ODd / BN, MTOT / BM);
    k_gemm2<<<g2, 512, smem2>>>(b_og, out);
}

// round 11
// speedup vs baseline: 1.0576x; 1.0576x over previous
#include <cuda_runtime.h>
#include <cstdint>
#include <cuda_bf16.h>
#include <mma.h>
#include <math.h>

using namespace nvcuda;

#define Bb   8
#define Ss   2048
#define Hh   8
#define IDd  256
#define ODd  256
#define KTOT 512
#define MTOT (Bb*Ss*Hh)       // 131072 tokens
#define BSN  (Bb*Ss)          // 16384
#define NCHUNK 16
#define CH   (Ss/NCHUNK)      // 128

// bf16 wmma GEMM tiling
#define BM   128
#define BN   64
#define BK   32               // bf16 elems per k-tile
#define LDP  40               // padded row stride (elems): 80 B, 16B-aligned rows
#define ASZ  (BM*LDP)         // 5120 elems per half per buffer
#define BSZ  (BN*LDP)         // 2560
#define STG  (2*ASZ + 2*BSZ)  // 15360 elems per stage (hi+lo A, hi+lo B)
#define SMEM_G (2*STG*2)      // 61440 bytes
#define CLD  68
#define NT   (KTOT/BK)        // 16

// ---------------- scratch ----------------------------------------------------
__device__ __align__(256) float          g_csum  [(size_t)MTOT * IDd];
__device__ __align__(256) __nv_bfloat16  g_x2hi  [(size_t)MTOT * KTOT];
__device__ __align__(256) __nv_bfloat16  g_x2lo  [(size_t)MTOT * KTOT];
__device__ __align__(256) float          g_gates [(size_t)3 * MTOT * ODd];
__device__ __align__(256) float          g_cell  [(size_t)MTOT * ODd];
__device__ __align__(256) __nv_bfloat16  g_cellhi[(size_t)MTOT * ODd];
__device__ __align__(256) __nv_bfloat16  g_celllo[(size_t)MTOT * ODd];
__device__ __align__(256) __nv_bfloat16  g_whhi  [3 * ODd * KTOT];
__device__ __align__(256) __nv_bfloat16  g_whlo  [3 * ODd * KTOT];
__device__ __align__(256) __nv_bfloat16  g_wohi  [ODd * KTOT];
__device__ __align__(256) __nv_bfloat16  g_wolo  [ODd * KTOT];
__device__ __align__(256) float          g_psum  [64 * NCHUNK * 256];
__device__ float g_mean[BSN];
__device__ float g_rstd[BSN];

__device__ __forceinline__ float sigmoidf_(float x) { return 1.f / (1.f + expf(-x)); }

__device__ __forceinline__ uint32_t smem_u32(const void* p) {
    uint32_t a;
    asm("{ .reg .u64 t; cvta.to.shared.u64 t, %1; cvt.u32.u64 %0, t; }" : "=r"(a) : "l"(p));
    return a;
}
__device__ __forceinline__ void cpa16(uint32_t dst, const void* src) {
    asm volatile("cp.async.cg.shared.global [%0], [%1], 16;\n" :: "r"(dst), "l"(src));
}
__device__ __forceinline__ void cpa_commit() { asm volatile("cp.async.commit_group;\n"); }
__device__ __forceinline__ void cpa_wait0()  { asm volatile("cp.async.wait_group 0;\n"); }

// ---------------- K1a/K1b: two-phase cumsum ----------------------------------
__global__ void k_cumsum_p1(const float* __restrict__ in) {
    int bh = blockIdx.x, chunk = blockIdx.y, d = threadIdx.x;
    int b = bh >> 3, h = bh & 7;
    const size_t stride = (size_t)Hh * IDd;
    size_t idx = ((size_t)b * Ss * Hh + h) * IDd + d + (size_t)chunk * CH * stride;
    float s = 0.f;
    for (int j = 0; j < CH; j += 8) {
        float v[8];
#pragma unroll
        for (int t = 0; t < 8; t++) v[t] = in[idx + (size_t)(j + t) * stride];
#pragma unroll
        for (int t = 0; t < 8; t++) s += v[t];
    }
    g_psum[(bh * NCHUNK + chunk) * 256 + d] = s;
}

__global__ void k_cumsum_p2(const float* __restrict__ in) {
    int bh = blockIdx.x, chunk = blockIdx.y, d = threadIdx.x;
    int b = bh >> 3, h = bh & 7;
    const size_t stride = (size_t)Hh * IDd;
    size_t idx = ((size_t)b * Ss * Hh + h) * IDd + d + (size_t)chunk * CH * stride;
    float acc = 0.f;
    for (int c = 0; c < chunk; c++) acc += g_psum[(bh * NCHUNK + c) * 256 + d];
    for (int j = 0; j < CH; j += 8) {
        float v[8];
#pragma unroll
        for (int t = 0; t < 8; t++) v[t] = in[idx + (size_t)(j + t) * stride];
#pragma unroll
        for (int t = 0; t < 8; t++) {
            acc += v[t];
            g_csum[idx + (size_t)(j + t) * stride] = acc;
        }
    }
}

// ---------------- K2: per-(b,s) stats ----------------------------------------
__global__ void k_stats() {
    size_t base = (size_t)blockIdx.x * 2048;
    float s1 = 0.f, s2 = 0.f;
    for (int i = threadIdx.x; i < 2048; i += 256) {
        float v = g_csum[base + i];
        s1 += v; s2 += v * v;
    }
#pragma unroll
    for (int o = 16; o; o >>= 1) {
        s1 += __shfl_down_sync(0xffffffffu, s1, o);
        s2 += __shfl_down_sync(0xffffffffu, s2, o);
    }
    __shared__ float a1[8], a2[8];
    int w = threadIdx.x >> 5, l = threadIdx.x & 31;
    if (l == 0) { a1[w] = s1; a2[w] = s2; }
    __syncthreads();
    if (threadIdx.x == 0) {
        float t1 = 0.f, t2 = 0.f;
#pragma unroll
        for (int i = 0; i < 8; i++) { t1 += a1[i]; t2 += a2[i]; }
        float mean = t1 * (1.f / 2048.f);
        float var  = t2 * (1.f / 2048.f) - mean * mean;
        g_mean[blockIdx.x] = mean;
        g_rstd[blockIdx.x] = rsqrtf(var + 1e-6f);
    }
}

// ---------------- K3: x2 = [in | LN(csum)] -> bf16 hi/lo ---------------------
__global__ void k_norm(const float* __restrict__ in,
                       const float* __restrict__ lnw,
                       const float* __restrict__ lnb) {
    int gi = blockIdx.x * 256 + threadIdx.x;
    int m = gi >> 7, part = gi & 127;
    float v[4];
    if (part < 64) {
        float4 x = ((const float4*)(in + (size_t)m * IDd))[part];
        v[0] = x.x; v[1] = x.y; v[2] = x.z; v[3] = x.w;
    } else {
        int d4 = part - 64;
        int h  = m & 7;
        float mu = g_mean[m >> 3], rs = g_rstd[m >> 3];
        float4 c = ((const float4*)(g_csum + (size_t)m * IDd))[d4];
        float4 w = ((const float4*)(lnw + h * IDd))[d4];
        float4 b = ((const float4*)(lnb + h * IDd))[d4];
        v[0] = (c.x - mu) * rs * w.x + b.x;
        v[1] = (c.y - mu) * rs * w.y + b.y;
        v[2] = (c.z - mu) * rs * w.z + b.z;
        v[3] = (c.w - mu) * rs * w.w + b.w;
    }
    unsigned short hs[4], ls[4];
#pragma unroll
    for (int j = 0; j < 4; j++) {
        __nv_bfloat16 h = __float2bfloat16(v[j]);
        __nv_bfloat16 l = __float2bfloat16(v[j] - __bfloat162float(h));
        hs[j] = __bfloat16_as_ushort(h);
        ls[j] = __bfloat16_as_ushort(l);
    }
    uint2 H, L;
    H.x = (uint32_t)hs[0] | ((uint32_t)hs[1] << 16);
    H.y = (uint32_t)hs[2] | ((uint32_t)hs[3] << 16);
    L.x = (uint32_t)ls[0] | ((uint32_t)ls[1] << 16);
    L.y = (uint32_t)ls[2] | ((uint32_t)ls[3] << 16);
    *(uint2*)(g_x2hi + (size_t)m * KTOT + part * 4) = H;
    *(uint2*)(g_x2lo + (size_t)m * KTOT + part * 4) = L;
}

// ---------------- K3b: weight bf16 hi/lo split -------------------------------
__global__ void k_wsplit(const float* __restrict__ Wh, const float* __restrict__ Wo) {
    int i = blockIdx.x * 256 + threadIdx.x;
    const int NH = 3 * ODd * KTOT;
    float x; __nv_bfloat16 *dh, *dl;
    if (i < NH) { x = Wh[i]; dh = g_whhi + i; dl = g_whlo + i; }
    else        { x = Wo[i - NH]; dh = g_wohi + (i - NH); dl = g_wolo + (i - NH); }
    __nv_bfloat16 h = __float2bfloat16(x);
    *dh = h;
    *dl = __float2bfloat16(x - __bfloat162float(h));
}

// ---------------- bf16 wmma GEMM (MODE 0: gates, MODE 1: output) -------------
// D = Ahi*Bhi + Ahi*Blo + Alo*Bhi  (single fp32 accumulator, 3-term split)
template<int MODE>
__global__ __launch_bounds__(256, 1)
void k_gemm_bf(const float* __restrict__ bias, float* __restrict__ outp) {
    extern __shared__ __align__(16) char smraw[];
    __nv_bfloat16* sm = (__nv_bfloat16*)smraw;
    float* Cs = (float*)smraw;                 // epilogue alias

    const int tid = threadIdx.x;
    const int n0  = blockIdx.x * BN;           // global N (768 for MODE0, 256 for MODE1)
    const int m0  = blockIdx.y * BM;
    const int warp = tid >> 5;
    const int wr = warp >> 1;                  // 0..3 (32 rows each)
    const int wc = warp & 1;                   // 0..1 (32 cols each)
    const uint32_t sb = smem_u32(sm);

    const __nv_bfloat16* Bhs = (MODE == 0) ? g_whhi : g_wohi;
    const __nv_bfloat16* Bls = (MODE == 0) ? g_whlo : g_wolo;

    wmma::fragment<wmma::accumulator, 16, 16, 16, float> acc[2][2];
#pragma unroll
    for (int t = 0; t < 2; t++)
#pragma unroll
        for (int u = 0; u < 2; u++) wmma::fill_fragment(acc[t][u], 0.f);

    auto issue = [&](int kt, int buf) {
        const int so = buf * STG;
        // A: hi+lo, 128 rows x 4 chunks(8 bf16) each = 1024 chunks
#pragma unroll
        for (int i = 0; i < 4; i++) {
            int cid = tid + i * 256;
            int half = cid >> 9, c = cid & 511;
            int r = c >> 2, cg = c & 3;
            const __nv_bfloat16* src;
            if (MODE == 0) {
                src = (half ? g_x2lo : g_x2hi) + (size_t)(m0 + r) * KTOT + kt * BK + cg * 8;
            } else {
                int gcol = kt * BK + cg * 8;
                src = (gcol < IDd)
                    ? (half ? g_x2lo : g_x2hi) + (size_t)(m0 + r) * KTOT + gcol
                    : (half ? g_celllo : g_cellhi) + (size_t)(m0 + r) * ODd + (gcol - IDd);
            }
            cpa16(sb + (uint32_t)(so + half * ASZ + r * LDP + cg * 8) * 2, src);
        }
        // B: hi+lo, 64 rows x 4 chunks = 512 chunks
#pragma unroll
        for (int i = 0; i < 2; i++) {
            int cid = tid + i * 256;
            int half = cid >> 8, c = cid & 255;
            int r = c >> 2, cg = c & 3;
            const __nv_bfloat16* src = (half ? Bls : Bhs)
                + (size_t)(n0 + r) * KTOT + kt * BK + cg * 8;
            cpa16(sb + (uint32_t)(so + 2 * ASZ + half * BSZ + r * LDP + cg * 8) * 2, src);
        }
    };

    issue(0, 0); cpa_commit();
    for (int kt = 0; kt < NT; kt++) {
        cpa_wait0();
        __syncthreads();
        if (kt + 1 < NT) { issue(kt + 1, (kt + 1) & 1); cpa_commit(); }
        const __nv_bfloat16* Ah = sm + (kt & 1) * STG;
        const __nv_bfloat16* Al = Ah + ASZ;
        const __nv_bfloat16* Bh = Ah + 2 * ASZ;
        const __nv_bfloat16* Bl = Bh + BSZ;
#pragma unroll
        for (int ks = 0; ks < 2; ks++) {
            wmma::fragment<wmma::matrix_a, 16, 16, 16, __nv_bfloat16, wmma::row_major> ah[2], al[2];
            wmma::fragment<wmma::matrix_b, 16, 16, 16, __nv_bfloat16, wmma::col_major> bh[2], bl[2];
#pragma unroll
            for (int t = 0; t < 2; t++) {
                wmma::load_matrix_sync(ah[t], Ah + (wr * 32 + t * 16) * LDP + ks * 16, LDP);
                wmma::load_matrix_sync(al[t], Al + (wr * 32 + t * 16) * LDP + ks * 16, LDP);
            }
#pragma unroll
            for (int u = 0; u < 2; u++) {
                wmma::load_matrix_sync(bh[u], Bh + (wc * 32 + u * 16) * LDP + ks * 16, LDP);
                wmma::load_matrix_sync(bl[u], Bl + (wc * 32 + u * 16) * LDP + ks * 16, LDP);
            }
#pragma unroll
            for (int t = 0; t < 2; t++)
#pragma unroll
                for (int u = 0; u < 2; u++) {
                    wmma::mma_sync(acc[t][u], ah[t], bh[u], acc[t][u]);
                    wmma::mma_sync(acc[t][u], ah[t], bl[u], acc[t][u]);
                    wmma::mma_sync(acc[t][u], al[t], bh[u], acc[t][u]);
                }
        }
        __syncthreads();
    }

    // epilogue
#pragma unroll
    for (int t = 0; t < 2; t++)
#pragma unroll
        for (int u = 0; u < 2; u++)
            wmma::store_matrix_sync(Cs + (wr * 32 + t * 16) * CLD + wc * 32 + u * 16,
                                    acc[t][u], CLD, wmma::mem_row_major);
    __syncthreads();

    const int gate = n0 >> 8;                  // MODE0 only
    const int col0 = n0 & 255;
#pragma unroll
    for (int j = 0; j < 8; j++) {
        int e = tid + j * 256;                 // 2048 float4s = 128 x 16
        int r = e >> 4, c4 = (e & 15) * 4;
        size_t row = (size_t)(m0 + r);
        float4 v;
        v.x = Cs[r * CLD + c4 + 0];
        v.y = Cs[r * CLD + c4 + 1];
        v.z = Cs[r * CLD + c4 + 2];
        v.w = Cs[r * CLD + c4 + 3];
        if (MODE == 0) {
            v.x += bias[n0 + c4 + 0];
            v.y += bias[n0 + c4 + 1];
            v.z += bias[n0 + c4 + 2];
            v.w += bias[n0 + c4 + 3];
            *(float4*)(g_gates + (size_t)gate * MTOT * ODd + row * ODd + col0 + c4) = v;
        } else {
            float4 cl = *(const float4*)(g_cell + row * ODd + n0 + c4);
            v.x = sigmoidf_(v.x + bias[n0 + c4 + 0]) * cl.x;
            v.y = sigmoidf_(v.y + bias[n0 + c4 + 1]) * cl.y;
            v.z = sigmoidf_(v.z + bias[n0 + c4 + 2]) * cl.z;
            v.w = sigmoidf_(v.w + bias[n0 + c4 + 3]) * cl.w;
            *(float4*)(outp + row * ODd + n0 + c4) = v;
        }
    }
}

// ---------------- K5: scan (nonlinearities fused) ----------------------------
__global__ void k_scan(const float* __restrict__ init_cx) {
    int lane = blockIdx.x * 128 + threadIdx.x;
    int od = lane & 255;
    int bh = lane >> 8;
    int h  = bh & 7;
    float c = init_cx[h * ODd + od];
    size_t idx = ((size_t)(bh >> 3) * Ss * Hh + h) * ODd + od;
    const size_t stride = (size_t)Hh * ODd;
    const float* gi = g_gates;
    const float* gf = g_gates + (size_t)MTOT * ODd;
    const float* gh = g_gates + (size_t)2 * MTOT * ODd;
    for (int s0 = 0; s0 < Ss; s0 += 16) {
        float iv[16], fv[16], hv[16];
#pragma unroll
        for (int j = 0; j < 16; j++) {
            iv[j] = gi[idx + (size_t)j * stride];
            fv[j] = gf[idx + (size_t)j * stride];
            hv[j] = gh[idx + (size_t)j * stride];
        }
#pragma unroll
        for (int j = 0; j < 16; j++) {
            float f  = sigmoidf_(fv[j]);
            float ig = sigmoidf_(iv[j]);
            float hh = hv[j] > 0.f ? hv[j] : 0.f;
            c = f * c + ig * hh;
            g_cell[idx + (size_t)j * stride] = c;
            __nv_bfloat16 chi = __float2bfloat16(c);
            g_cellhi[idx + (size_t)j * stride] = chi;
            g_celllo[idx + (size_t)j * stride] = __float2bfloat16(c - __bfloat162float(chi));
        }
        idx += 16 * stride;
    }
}

// ---------------- launcher ---------------------------------------------------
extern "C" void kernel_launch(void* const* d_in, const int* in_sizes, int n_in,
                              void* d_out, int out_size) {
    const float* in      = (const float*)d_in[0];
    const float* W_hid   = (const float*)d_in[1];
    const float* b_hid   = (const float*)d_in[2];
    const float* W_og    = (const float*)d_in[3];
    const float* b_og    = (const float*)d_in[4];
    const float* ln_w    = (const float*)d_in[5];
    const float* ln_b    = (const float*)d_in[6];
    const float* init_cx = (const float*)d_in[7];
    float* out = (float*)d_out;

    cudaFuncSetAttribute(k_gemm_bf<0>, cudaFuncAttributeMaxDynamicSharedMemorySize, SMEM_G);
    cudaFuncSetAttribute(k_gemm_bf<1>, cudaFuncAttributeMaxDynamicSharedMemorySize, SMEM_G);

    k_wsplit<<<(3 * ODd * KTOT + ODd * KTOT) / 256, 256>>>(W_hid, W_og);

    dim3 gcs(Bb * Hh, NCHUNK);
    k_cumsum_p1<<<gcs, 256>>>(in);
    k_cumsum_p2<<<gcs, 256>>>(in);
    k_stats<<<BSN, 256>>>();
    k_norm<<<(MTOT * 128) / 256, 256>>>(in, ln_w, ln_b);

    // 6th launch -> captured by ncu (-s 5 -c 1)
    k_gemm_bf<0><<<dim3(12, MTOT / BM), 256, SMEM_G>>>(b_hid, nullptr);

    k_scan<<<(Bb * Hh * ODd) / 128, 128>>>(init_cx);

    k_gemm_bf<1><<<dim3(4, MTOT / BM), 256, SMEM_G>>>(b_og, out);
}

// round 14
// speedup vs baseline: 1.3715x; 1.2968x over previous
#include <cuda_runtime.h>
#include <cstdint>
#include <cuda_bf16.h>
#include <mma.h>
#include <math.h>

using namespace nvcuda;

#define Bb   8
#define Ss   2048
#define Hh   8
#define IDd  256
#define ODd  256
#define KTOT 512
#define MTOT (Bb*Ss*Hh)       // 131072 tokens
#define BSN  (Bb*Ss)          // 16384

// bf16 wmma GEMM tiling
#define BM   128
#define BN   64
#define BK   32
#define LDP  40
#define ASZ  (BM*LDP)
#define BSZ  (BN*LDP)
#define STG  (2*ASZ + 2*BSZ)
#define SMEM_G (2*STG*2)      // 61440 bytes
#define CLD  68
#define NT   (KTOT/BK)        // 16

// ---------------- scratch ----------------------------------------------------
__device__ __align__(256) float          g_csum  [(size_t)MTOT * IDd];
__device__ __align__(256) __nv_bfloat16  g_x2hi  [(size_t)MTOT * KTOT];
__device__ __align__(256) __nv_bfloat16  g_x2lo  [(size_t)MTOT * KTOT];
__device__ __align__(256) float          g_gates [(size_t)3 * MTOT * ODd];
__device__ __align__(256) float          g_cell  [(size_t)MTOT * ODd];
__device__ __align__(256) __nv_bfloat16  g_cellhi[(size_t)MTOT * ODd];
__device__ __align__(256) __nv_bfloat16  g_celllo[(size_t)MTOT * ODd];
__device__ __align__(256) __nv_bfloat16  g_whhi  [3 * ODd * KTOT];
__device__ __align__(256) __nv_bfloat16  g_whlo  [3 * ODd * KTOT];
__device__ __align__(256) __nv_bfloat16  g_wohi  [ODd * KTOT];
__device__ __align__(256) __nv_bfloat16  g_wolo  [ODd * KTOT];

__device__ __forceinline__ float sigmoidf_(float x) { return 1.f / (1.f + expf(-x)); }

__device__ __forceinline__ uint32_t smem_u32(const void* p) {
    uint32_t a;
    asm("{ .reg .u64 t; cvta.to.shared.u64 t, %1; cvt.u32.u64 %0, t; }" : "=r"(a) : "l"(p));
    return a;
}
__device__ __forceinline__ void cpa16(uint32_t dst, const void* src) {
    asm volatile("cp.async.cg.shared.global [%0], [%1], 16;\n" :: "r"(dst), "l"(src));
}
__device__ __forceinline__ void cpa_commit() { asm volatile("cp.async.commit_group;\n"); }
__device__ __forceinline__ void cpa_wait0()  { asm volatile("cp.async.wait_group 0;\n"); }

__device__ __forceinline__ void bf_split(float v, __nv_bfloat16& h, __nv_bfloat16& l) {
    h = __float2bfloat16(v);
    l = __float2bfloat16(v - __bfloat162float(h));
}

// ---------------- K1: weight bf16 hi/lo split --------------------------------
__global__ void k_wsplit(const float* __restrict__ Wh, const float* __restrict__ Wo) {
    int i = blockIdx.x * 256 + threadIdx.x;
    const int NH = 3 * ODd * KTOT;
    float x; __nv_bfloat16 *dh, *dl;
    if (i < NH) { x = Wh[i]; dh = g_whhi + i; dl = g_whlo + i; }
    else        { x = Wo[i - NH]; dh = g_wohi + (i - NH); dl = g_wolo + (i - NH); }
    bf_split(x, *dh, *dl);
}

// ---------------- K2: cumsum over S (single pass, 64 CTAs, MLP=16) -----------
__global__ void k_cumsum(const float* __restrict__ in) {
    int bh = blockIdx.x;            // 0..63
    int d  = threadIdx.x;           // 0..255
    int b  = bh >> 3, h = bh & 7;
    size_t base = ((size_t)b * Ss * Hh + h) * IDd + d;
    const size_t stride = (size_t)Hh * IDd;
    float acc = 0.f;
    for (int s0 = 0; s0 < Ss; s0 += 16) {
        float v[16];
#pragma unroll
        for (int j = 0; j < 16; j++) v[j] = in[base + (size_t)(s0 + j) * stride];
#pragma unroll
        for (int j = 0; j < 16; j++) {
            acc += v[j];
            g_csum[base + (size_t)(s0 + j) * stride] = acc;
        }
    }
}

// ---------------- K3: fused stats + norm (block = token) ---------------------
__global__ void k_statsnorm(const float* __restrict__ in,
                            const float* __restrict__ lnw,
                            const float* __restrict__ lnb) {
    const int bs = blockIdx.x;                  // 0..16383
    const int t  = threadIdx.x;                 // 0..255
    const size_t base = (size_t)bs * 2048;      // 8 m-rows x 256, contiguous

    const float4* cs = (const float4*)(g_csum + base);
    float4 c0 = cs[t * 2], c1 = cs[t * 2 + 1];

    float s1 = c0.x + c0.y + c0.z + c0.w + c1.x + c1.y + c1.z + c1.w;
    float s2 = c0.x*c0.x + c0.y*c0.y + c0.z*c0.z + c0.w*c0.w
             + c1.x*c1.x + c1.y*c1.y + c1.z*c1.z + c1.w*c1.w;
#pragma unroll
    for (int o = 16; o; o >>= 1) {
        s1 += __shfl_down_sync(0xffffffffu, s1, o);
        s2 += __shfl_down_sync(0xffffffffu, s2, o);
    }
    __shared__ float a1[8], a2[8], s_mr[2];
    int w = t >> 5, l = t & 31;
    if (l == 0) { a1[w] = s1; a2[w] = s2; }
    __syncthreads();
    if (t == 0) {
        float t1 = 0.f, t2 = 0.f;
#pragma unroll
        for (int i = 0; i < 8; i++) { t1 += a1[i]; t2 += a2[i]; }
        float mean = t1 * (1.f / 2048.f);
        float var  = t2 * (1.f / 2048.f) - mean * mean;
        s_mr[0] = mean;
        s_mr[1] = rsqrtf(var + 1e-6f);
    }
    __syncthreads();
    const float mu = s_mr[0], rs = s_mr[1];

#pragma unroll
    for (int i = 0; i < 2; i++) {
        int j = t * 2 + i;
        int h = j >> 6, col4 = j & 63;
        float4 c = (i == 0) ? c0 : c1;
        float4 wv = ((const float4*)(lnw + h * IDd))[col4];
        float4 bv = ((const float4*)(lnb + h * IDd))[col4];
        float v[4] = {
            (c.x - mu) * rs * wv.x + bv.x,
            (c.y - mu) * rs * wv.y + bv.y,
            (c.z - mu) * rs * wv.z + bv.z,
            (c.w - mu) * rs * wv.w + bv.w };
        unsigned short hs[4], ls[4];
#pragma unroll
        for (int q = 0; q < 4; q++) {
            __nv_bfloat16 hh, ll; bf_split(v[q], hh, ll);
            hs[q] = __bfloat16_as_ushort(hh);
            ls[q] = __bfloat16_as_ushort(ll);
        }
        size_t m = (size_t)bs * 8 + h;
        uint2 H = { (uint32_t)hs[0] | ((uint32_t)hs[1] << 16),
                    (uint32_t)hs[2] | ((uint32_t)hs[3] << 16) };
        uint2 L = { (uint32_t)ls[0] | ((uint32_t)ls[1] << 16),
                    (uint32_t)ls[2] | ((uint32_t)ls[3] << 16) };
        *(uint2*)(g_x2hi + m * KTOT + IDd + col4 * 4) = H;
        *(uint2*)(g_x2lo + m * KTOT + IDd + col4 * 4) = L;
    }
#pragma unroll
    for (int i = 0; i < 2; i++) {
        int j = t * 2 + i;
        int h = j >> 6, col4 = j & 63;
        size_t m = (size_t)bs * 8 + h;
        float4 x = ((const float4*)(in + m * IDd))[col4];
        float v[4] = { x.x, x.y, x.z, x.w };
        unsigned short hs[4], ls[4];
#pragma unroll
        for (int q = 0; q < 4; q++) {
            __nv_bfloat16 hh, ll; bf_split(v[q], hh, ll);
            hs[q] = __bfloat16_as_ushort(hh);
            ls[q] = __bfloat16_as_ushort(ll);
        }
        uint2 H = { (uint32_t)hs[0] | ((uint32_t)hs[1] << 16),
                    (uint32_t)hs[2] | ((uint32_t)hs[3] << 16) };
        uint2 L = { (uint32_t)ls[0] | ((uint32_t)ls[1] << 16),
                    (uint32_t)ls[2] | ((uint32_t)ls[3] << 16) };
        *(uint2*)(g_x2hi + m * KTOT + col4 * 4) = H;
        *(uint2*)(g_x2lo + m * KTOT + col4 * 4) = L;
    }
}

// ---------------- bf16 wmma GEMM (MODE 0: gates, MODE 1: output) -------------
// D = Ahi*Bhi + Ahi*Blo + Alo*Bhi ; launch_bounds(256,2) -> 2 CTAs/SM
template<int MODE>
__global__ __launch_bounds__(256, 2)
void k_gemm_bf(const float* __restrict__ bias, float* __restrict__ outp) {
    extern __shared__ __align__(16) char smraw[];
    __nv_bfloat16* sm = (__nv_bfloat16*)smraw;
    float* Cs = (float*)smraw;

    const int tid = threadIdx.x;
    const int n0  = blockIdx.x * BN;
    const int m0  = blockIdx.y * BM;
    const int warp = tid >> 5;
    const int wr = warp >> 1;
    const int wc = warp & 1;
    const uint32_t sb = smem_u32(sm);

    const __nv_bfloat16* Bhs = (MODE == 0) ? g_whhi : g_wohi;
    const __nv_bfloat16* Bls = (MODE == 0) ? g_whlo : g_wolo;

    wmma::fragment<wmma::accumulator, 16, 16, 16, float> acc[2][2];
#pragma unroll
    for (int t = 0; t < 2; t++)
#pragma unroll
        for (int u = 0; u < 2; u++) wmma::fill_fragment(acc[t][u], 0.f);

    auto issue = [&](int kt, int buf) {
        const int so = buf * STG;
#pragma unroll
        for (int i = 0; i < 4; i++) {
            int cid = tid + i * 256;
            int half = cid >> 9, c = cid & 511;
            int r = c >> 2, cg = c & 3;
            const __nv_bfloat16* src;
            if (MODE == 0) {
                src = (half ? g_x2lo : g_x2hi) + (size_t)(m0 + r) * KTOT + kt * BK + cg * 8;
            } else {
                int gcol = kt * BK + cg * 8;
                src = (gcol < IDd)
                    ? (half ? g_x2lo : g_x2hi) + (size_t)(m0 + r) * KTOT + gcol
                    : (half ? g_celllo : g_cellhi) + (size_t)(m0 + r) * ODd + (gcol - IDd);
            }
            cpa16(sb + (uint32_t)(so + half * ASZ + r * LDP + cg * 8) * 2, src);
        }
#pragma unroll
        for (int i = 0; i < 2; i++) {
            int cid = tid + i * 256;
            int half = cid >> 8, c = cid & 255;
            int r = c >> 2, cg = c & 3;
            const __nv_bfloat16* src = (half ? Bls : Bhs)
                + (size_t)(n0 + r) * KTOT + kt * BK + cg * 8;
            cpa16(sb + (uint32_t)(so + 2 * ASZ + half * BSZ + r * LDP + cg * 8) * 2, src);
        }
    };

    issue(0, 0); cpa_commit();
    for (int kt = 0; kt < NT; kt++) {
        cpa_wait0();
        __syncthreads();
        if (kt + 1 < NT) { issue(kt + 1, (kt + 1) & 1); cpa_commit(); }
        const __nv_bfloat16* Ah = sm + (kt & 1) * STG;
        const __nv_bfloat16* Al = Ah + ASZ;
        const __nv_bfloat16* Bh = Ah + 2 * ASZ;
        const __nv_bfloat16* Bl = Bh + BSZ;
#pragma unroll
        for (int ks = 0; ks < 2; ks++) {
            wmma::fragment<wmma::matrix_a, 16, 16, 16, __nv_bfloat16, wmma::row_major> ah[2], al[2];
            wmma::fragment<wmma::matrix_b, 16, 16, 16, __nv_bfloat16, wmma::col_major> bh[2], bl[2];
#pragma unroll
            for (int t = 0; t < 2; t++) {
                wmma::load_matrix_sync(ah[t], Ah + (wr * 32 + t * 16) * LDP + ks * 16, LDP);
                wmma::load_matrix_sync(al[t], Al + (wr * 32 + t * 16) * LDP + ks * 16, LDP);
            }
#pragma unroll
            for (int u = 0; u < 2; u++) {
                wmma::load_matrix_sync(bh[u], Bh + (wc * 32 + u * 16) * LDP + ks * 16, LDP);
                wmma::load_matrix_sync(bl[u], Bl + (wc * 32 + u * 16) * LDP + ks * 16, LDP);
            }
#pragma unroll
            for (int t = 0; t < 2; t++)
#pragma unroll
                for (int u = 0; u < 2; u++) {
                    wmma::mma_sync(acc[t][u], ah[t], bh[u], acc[t][u]);
                    wmma::mma_sync(acc[t][u], ah[t], bl[u], acc[t][u]);
                    wmma::mma_sync(acc[t][u], al[t], bh[u], acc[t][u]);
                }
        }
        __syncthreads();
    }

#pragma unroll
    for (int t = 0; t < 2; t++)
#pragma unroll
        for (int u = 0; u < 2; u++)
            wmma::store_matrix_sync(Cs + (wr * 32 + t * 16) * CLD + wc * 32 + u * 16,
                                    acc[t][u], CLD, wmma::mem_row_major);
    __syncthreads();

    const int gate = n0 >> 8;
    const int col0 = n0 & 255;
#pragma unroll
    for (int j = 0; j < 8; j++) {
        int e = tid + j * 256;
        int r = e >> 4, c4 = (e & 15) * 4;
        size_t row = (size_t)(m0 + r);
        float4 v;
        v.x = Cs[r * CLD + c4 + 0];
        v.y = Cs[r * CLD + c4 + 1];
        v.z = Cs[r * CLD + c4 + 2];
        v.w = Cs[r * CLD + c4 + 3];
        if (MODE == 0) {
            v.x += bias[n0 + c4 + 0];
            v.y += bias[n0 + c4 + 1];
            v.z += bias[n0 + c4 + 2];
            v.w += bias[n0 + c4 + 3];
            *(float4*)(g_gates + (size_t)gate * MTOT * ODd + row * ODd + col0 + c4) = v;
        } else {
            float4 cl = *(const float4*)(g_cell + row * ODd + n0 + c4);
            v.x = sigmoidf_(v.x + bias[n0 + c4 + 0]) * cl.x;
            v.y = sigmoidf_(v.y + bias[n0 + c4 + 1]) * cl.y;
            v.z = sigmoidf_(v.z + bias[n0 + c4 + 2]) * cl.z;
            v.w = sigmoidf_(v.w + bias[n0 + c4 + 3]) * cl.w;
            *(float4*)(outp + row * ODd + n0 + c4) = v;
        }
    }
}

// ---------------- K5: scan (nonlinearities fused) ----------------------------
__global__ void k_scan(const float* __restrict__ init_cx) {
    int lane = blockIdx.x * 128 + threadIdx.x;
    int od = lane & 255;
    int bh = lane >> 8;
    int h  = bh & 7;
    float c = init_cx[h * ODd + od];
    size_t idx = ((size_t)(bh >> 3) * Ss * Hh + h) * ODd + od;
    const size_t stride = (size_t)Hh * ODd;
    const float* gi = g_gates;
    const float* gf = g_gates + (size_t)MTOT * ODd;
    const float* gh = g_gates + (size_t)2 * MTOT * ODd;
    for (int s0 = 0; s0 < Ss; s0 += 16) {
        float iv[16], fv[16], hv[16];
#pragma unroll
        for (int j = 0; j < 16; j++) {
            iv[j] = gi[idx + (size_t)j * stride];
            fv[j] = gf[idx + (size_t)j * stride];
            hv[j] = gh[idx + (size_t)j * stride];
        }
#pragma unroll
        for (int j = 0; j < 16; j++) {
            float f  = sigmoidf_(fv[j]);
            float ig = sigmoidf_(iv[j]);
            float hh = hv[j] > 0.f ? hv[j] : 0.f;
            c = f * c + ig * hh;
            g_cell[idx + (size_t)j * stride] = c;
            __nv_bfloat16 chi, clo;
            bf_split(c, chi, clo);
            g_cellhi[idx + (size_t)j * stride] = chi;
            g_celllo[idx + (size_t)j * stride] = clo;
        }
        idx += 16 * stride;
    }
}

// ---------------- launcher ---------------------------------------------------
extern "C" void kernel_launch(void* const* d_in, const int* in_sizes, int n_in,
                              void* d_out, int out_size) {
    const float* in      = (const float*)d_in[0];
    const float* W_hid   = (const float*)d_in[1];
    const float* b_hid   = (const float*)d_in[2];
    const float* W_og    = (const float*)d_in[3];
    const float* b_og    = (const float*)d_in[4];
    const float* ln_w    = (const float*)d_in[5];
    const float* ln_b    = (const float*)d_in[6];
    const float* init_cx = (const float*)d_in[7];
    float* out = (float*)d_out;

    cudaFuncSetAttribute(k_gemm_bf<0>, cudaFuncAttributeMaxDynamicSharedMemorySize, SMEM_G);
    cudaFuncSetAttribute(k_gemm_bf<1>, cudaFuncAttributeMaxDynamicSharedMemorySize, SMEM_G);

    k_wsplit<<<(3 * ODd * KTOT + ODd * KTOT) / 256, 256>>>(W_hid, W_og);   // #1
    k_cumsum<<<Bb * Hh, 256>>>(in);                                        // #2
    k_statsnorm<<<BSN, 256>>>(in, ln_w, ln_b);                             // #3
    k_gemm_bf<0><<<dim3(12, MTOT / BM), 256, SMEM_G>>>(b_hid, nullptr);    // #4 <- ncu
    k_scan<<<(Bb * Hh * ODd) / 128, 128>>>(init_cx);                       // #5
    k_gemm_bf<1><<<dim3(4, MTOT / BM), 256, SMEM_G>>>(b_og, out);          // #6
}